// round 2
// baseline (speedup 1.0000x reference)
#include <cuda_runtime.h>

#define EMBED 64
#define MAX_NODES 100000

// Scratch: h = relu(x @ W^T + b), per-node edge counts, dtype flag.
__device__ float g_h[(size_t)MAX_NODES * EMBED];
__device__ int   g_counts[MAX_NODES];
__device__ int   g_is64;   // 1 if edge_index is int64, 0 if int32

// ---------------------------------------------------------------------------
// Kernel A: sniff edge_index dtype. If the buffer is really int64 with values
// in [0, 1e5), every u64 word has a zero high half and a small low half. If it
// is int32, a u64 word packs two random indices -> high half nonzero almost
// surely (false-positive prob ~ (1e-5)^8).
// ---------------------------------------------------------------------------
__global__ void sniff_kernel(const unsigned long long* __restrict__ ei) {
    int ok64 = 1;
    #pragma unroll
    for (int i = 0; i < 8; i++) {
        unsigned long long v = ei[i];
        if ((v >> 32) != 0ull || (v & 0xffffffffull) >= (1u << 28)) ok64 = 0;
    }
    g_is64 = ok64;
}

// ---------------------------------------------------------------------------
// Kernel 0: zero the output (poisoned by harness) and the counts array.
// ---------------------------------------------------------------------------
__global__ void zero_kernel(float4* __restrict__ out4, int n_f4, int n_nodes) {
    int i = blockIdx.x * blockDim.x + threadIdx.x;
    if (i < n_f4) out4[i] = make_float4(0.f, 0.f, 0.f, 0.f);
    if (i < n_nodes) g_counts[i] = 0;
}

// ---------------------------------------------------------------------------
// Kernel 1: h[n][o] = relu(b[o] + sum_d x[n][d] * W[o][d])
// One thread per node. W (16KB) staged in smem, read as broadcast LDS.128.
// ---------------------------------------------------------------------------
__global__ void __launch_bounds__(256) gemm_relu_kernel(
    const float* __restrict__ x,
    const float* __restrict__ W,
    const float* __restrict__ b,
    int n_nodes)
{
    __shared__ float4 ws[EMBED][EMBED / 4];  // ws[o][d4] = W[o][4*d4..4*d4+3]
    __shared__ float  bs[EMBED];

    int tid = threadIdx.x;
    const float4* W4 = (const float4*)W;
    #pragma unroll
    for (int i = tid; i < EMBED * EMBED / 4; i += 256)
        ((float4*)ws)[i] = W4[i];
    if (tid < EMBED) bs[tid] = b[tid];
    __syncthreads();

    int n = blockIdx.x * 256 + tid;
    if (n >= n_nodes) return;

    float4 xr[16];
    const float4* xp = (const float4*)(x + (size_t)n * EMBED);
    #pragma unroll
    for (int i = 0; i < 16; i++) xr[i] = xp[i];

    float4* hp = (float4*)(g_h + (size_t)n * EMBED);
    #pragma unroll 2
    for (int o = 0; o < EMBED; o += 4) {
        float a0 = bs[o + 0], a1 = bs[o + 1], a2 = bs[o + 2], a3 = bs[o + 3];
        #pragma unroll
        for (int d4 = 0; d4 < 16; d4++) {
            float4 xv = xr[d4];
            float4 w0 = ws[o + 0][d4];
            float4 w1 = ws[o + 1][d4];
            float4 w2 = ws[o + 2][d4];
            float4 w3 = ws[o + 3][d4];
            a0 += xv.x * w0.x + xv.y * w0.y + xv.z * w0.z + xv.w * w0.w;
            a1 += xv.x * w1.x + xv.y * w1.y + xv.z * w1.z + xv.w * w1.w;
            a2 += xv.x * w2.x + xv.y * w2.y + xv.z * w2.z + xv.w * w2.w;
            a3 += xv.x * w3.x + xv.y * w3.y + xv.z * w3.z + xv.w * w3.w;
        }
        hp[o >> 2] = make_float4(fmaxf(a0, 0.f), fmaxf(a1, 0.f),
                                 fmaxf(a2, 0.f), fmaxf(a3, 0.f));
    }
}

// ---------------------------------------------------------------------------
// Kernel 2: scatter. 16 threads per edge; thread j handles float4 j of the row.
// out[src] += h[tgt]  (red.global.add.v4.f32), counts[src] += 1.
// Indices decoded per the sniffed dtype flag.
// ---------------------------------------------------------------------------
__global__ void __launch_bounds__(256) scatter_kernel(
    const void* __restrict__ ei_raw,   // [2, E] int32 or int64
    int n_edges,
    float* __restrict__ out)
{
    int t = blockIdx.x * 256 + threadIdx.x;
    int e = t >> 4;
    int j = t & 15;
    if (e >= n_edges) return;

    int src, tgt;
    if (g_is64) {
        const long long* ei = (const long long*)ei_raw;
        src = (int)__ldg(&ei[e]);
        tgt = (int)__ldg(&ei[(size_t)n_edges + e]);
    } else {
        const int* ei = (const int*)ei_raw;
        src = __ldg(&ei[e]);
        tgt = __ldg(&ei[(size_t)n_edges + e]);
    }

    float4 v = ((const float4*)g_h)[(size_t)tgt * 16 + j];
    float4* dst = ((float4*)out) + (size_t)src * 16 + j;

    asm volatile("red.global.add.v4.f32 [%0], {%1, %2, %3, %4};"
                 :: "l"(dst), "f"(v.x), "f"(v.y), "f"(v.z), "f"(v.w)
                 : "memory");

    if (j == 0) atomicAdd(&g_counts[src], 1);
}

// ---------------------------------------------------------------------------
// Kernel 3: normalize. out[n] /= max(counts[n], 1). 16 threads per node.
// ---------------------------------------------------------------------------
__global__ void __launch_bounds__(256) norm_kernel(float4* __restrict__ out4,
                                                   int n_nodes)
{
    int t = blockIdx.x * 256 + threadIdx.x;
    int n = t >> 4;
    if (n >= n_nodes) return;
    float inv = 1.0f / fmaxf((float)g_counts[n], 1.0f);
    float4 v = out4[t];
    v.x *= inv; v.y *= inv; v.z *= inv; v.w *= inv;
    out4[t] = v;
}

// ---------------------------------------------------------------------------
// Launch
// ---------------------------------------------------------------------------
extern "C" void kernel_launch(void* const* d_in, const int* in_sizes, int n_in,
                              void* d_out, int out_size)
{
    const float* x  = (const float*)d_in[0];
    const void*  ei = d_in[1];
    const float* W  = (const float*)d_in[2];
    const float* b  = (const float*)d_in[3];
    float*       out = (float*)d_out;

    int N = in_sizes[0] / EMBED;     // 100000
    int E = in_sizes[1] / 2;         // 1600000

    sniff_kernel<<<1, 1>>>((const unsigned long long*)ei);

    int n_f4 = out_size / 4;         // output float4 count
    int zthreads = (n_f4 > N) ? n_f4 : N;
    zero_kernel<<<(zthreads + 255) / 256, 256>>>((float4*)out, n_f4, N);

    gemm_relu_kernel<<<(N + 255) / 256, 256>>>(x, W, b, N);

    long long st = (long long)E * 16;
    scatter_kernel<<<(int)((st + 255) / 256), 256>>>(ei, E, out);

    long long nt = (long long)N * 16;
    norm_kernel<<<(int)((nt + 255) / 256), 256>>>((float4*)out, N);
}

// round 3
// speedup vs baseline: 1.3679x; 1.3679x over previous
#include <cuda_runtime.h>

#define EMBED 64
#define MAX_NODES 100000
#define MAX_EDGES 1600000
#define SCAN_BLK 1024

// Scratch
__device__ float g_h[(size_t)MAX_NODES * EMBED];    // relu(x@W^T+b)
__device__ int   g_hist[MAX_NODES];                 // degree per src node
__device__ int   g_start[MAX_NODES];                // exclusive scan of hist
__device__ int   g_cursor[MAX_NODES];               // running fill cursor
__device__ int   g_bsum[128];                       // scan block sums
__device__ int   g_stgt[MAX_EDGES];                 // tgt indices sorted by src
__device__ int   g_is64;                            // edge_index dtype flag

#define FMA2(acc, a, b) \
    asm("fma.rn.f32x2 %0, %1, %2, %0;" : "+l"(acc) : "l"(a), "l"(b))

__device__ __forceinline__ unsigned long long pack2(float lo, float hi) {
    unsigned long long r;
    asm("mov.b64 %0, {%1, %2};" : "=l"(r) : "f"(lo), "f"(hi));
    return r;
}
__device__ __forceinline__ float unpack_lo(unsigned long long v) {
    float lo, hi;
    asm("mov.b64 {%0, %1}, %2;" : "=f"(lo), "=f"(hi) : "l"(v));
    return lo;
}
__device__ __forceinline__ float unpack_hi(unsigned long long v) {
    float lo, hi;
    asm("mov.b64 {%0, %1}, %2;" : "=f"(lo), "=f"(hi) : "l"(v));
    return hi;
}

// ---------------------------------------------------------------------------
// Kernel 0: zero histogram; thread (0,0) also sniffs edge_index dtype.
// int64 with values < 1e5 => every u64 word has zero high half, small low half.
// ---------------------------------------------------------------------------
__global__ void init_kernel(const unsigned long long* __restrict__ ei, int n_nodes) {
    int i = blockIdx.x * blockDim.x + threadIdx.x;
    if (i < n_nodes) g_hist[i] = 0;
    if (i == 0) {
        int ok64 = 1;
        #pragma unroll
        for (int k = 0; k < 8; k++) {
            unsigned long long v = ei[k];
            if ((v >> 32) != 0ull || (v & 0xffffffffull) >= (1u << 28)) ok64 = 0;
        }
        g_is64 = ok64;
    }
}

// ---------------------------------------------------------------------------
// Kernel 1: h = relu(x @ W^T + b) using packed fma.rn.f32x2 (2 MACs/instr).
// One thread per node; W staged in smem, read as broadcast LDS.64 pairs.
// ---------------------------------------------------------------------------
__global__ void __launch_bounds__(256) gemm_relu_kernel(
    const float* __restrict__ x,
    const float* __restrict__ W,
    const float* __restrict__ b,
    int n_nodes)
{
    __shared__ float ws[EMBED * EMBED];   // row-major W[o][d]
    __shared__ float bs[EMBED];

    int tid = threadIdx.x;
    const float4* W4 = (const float4*)W;
    #pragma unroll
    for (int i = tid; i < EMBED * EMBED / 4; i += 256)
        ((float4*)ws)[i] = W4[i];
    if (tid < EMBED) bs[tid] = b[tid];
    __syncthreads();

    int n = blockIdx.x * 256 + tid;
    if (n >= n_nodes) return;

    // Load x row as float4, pack into 32 f32x2 pairs.
    unsigned long long x2[EMBED / 2];
    const float4* xp = (const float4*)(x + (size_t)n * EMBED);
    #pragma unroll
    for (int i = 0; i < 16; i++) {
        float4 v = xp[i];
        x2[2 * i]     = pack2(v.x, v.y);
        x2[2 * i + 1] = pack2(v.z, v.w);
    }

    float4* hp = (float4*)(g_h + (size_t)n * EMBED);
    #pragma unroll 1
    for (int o = 0; o < EMBED; o += 4) {
        unsigned long long a0 = 0ull, a1 = 0ull, a2 = 0ull, a3 = 0ull;
        const unsigned long long* w0 = (const unsigned long long*)(ws + (o + 0) * EMBED);
        const unsigned long long* w1 = (const unsigned long long*)(ws + (o + 1) * EMBED);
        const unsigned long long* w2 = (const unsigned long long*)(ws + (o + 2) * EMBED);
        const unsigned long long* w3 = (const unsigned long long*)(ws + (o + 3) * EMBED);
        #pragma unroll
        for (int d2 = 0; d2 < EMBED / 2; d2++) {
            unsigned long long xv = x2[d2];
            FMA2(a0, xv, w0[d2]);
            FMA2(a1, xv, w1[d2]);
            FMA2(a2, xv, w2[d2]);
            FMA2(a3, xv, w3[d2]);
        }
        float r0 = bs[o + 0] + unpack_lo(a0) + unpack_hi(a0);
        float r1 = bs[o + 1] + unpack_lo(a1) + unpack_hi(a1);
        float r2 = bs[o + 2] + unpack_lo(a2) + unpack_hi(a2);
        float r3 = bs[o + 3] + unpack_lo(a3) + unpack_hi(a3);
        hp[o >> 2] = make_float4(fmaxf(r0, 0.f), fmaxf(r1, 0.f),
                                 fmaxf(r2, 0.f), fmaxf(r3, 0.f));
    }
}

// ---------------------------------------------------------------------------
// Kernel 2: histogram of src indices.
// ---------------------------------------------------------------------------
__global__ void hist_kernel(const void* __restrict__ ei_raw, int n_edges) {
    int e = blockIdx.x * blockDim.x + threadIdx.x;
    if (e >= n_edges) return;
    int src = g_is64 ? (int)((const long long*)ei_raw)[e]
                     : ((const int*)ei_raw)[e];
    atomicAdd(&g_hist[src], 1);
}

// ---------------------------------------------------------------------------
// Kernel 3a: per-block exclusive scan (Hillis-Steele, 1024 threads).
// ---------------------------------------------------------------------------
__global__ void __launch_bounds__(SCAN_BLK) scan1_kernel(int n_nodes) {
    __shared__ int s[SCAN_BLK];
    int t = threadIdx.x;
    int i = blockIdx.x * SCAN_BLK + t;
    int v = (i < n_nodes) ? g_hist[i] : 0;
    s[t] = v;
    __syncthreads();
    #pragma unroll
    for (int off = 1; off < SCAN_BLK; off <<= 1) {
        int add = (t >= off) ? s[t - off] : 0;
        __syncthreads();
        s[t] += add;
        __syncthreads();
    }
    if (i < n_nodes) g_start[i] = s[t] - v;           // exclusive
    if (t == SCAN_BLK - 1) g_bsum[blockIdx.x] = s[t]; // block total
}

// Kernel 3b: exclusive scan of block sums (<=128 blocks).
__global__ void scan2_kernel(int n_blocks) {
    __shared__ int s[128];
    int t = threadIdx.x;
    int v = (t < n_blocks) ? g_bsum[t] : 0;
    s[t] = v;
    __syncthreads();
    #pragma unroll
    for (int off = 1; off < 128; off <<= 1) {
        int add = (t >= off) ? s[t - off] : 0;
        __syncthreads();
        s[t] += add;
        __syncthreads();
    }
    g_bsum[t] = s[t] - v;
}

// Kernel 3c: add block offsets; init cursors.
__global__ void __launch_bounds__(SCAN_BLK) scan3_kernel(int n_nodes) {
    int i = blockIdx.x * SCAN_BLK + threadIdx.x;
    if (i >= n_nodes) return;
    int v = g_start[i] + g_bsum[blockIdx.x];
    g_start[i]  = v;
    g_cursor[i] = v;
}

// ---------------------------------------------------------------------------
// Kernel 4: reorder tgt indices grouped by src.
// ---------------------------------------------------------------------------
__global__ void reorder_kernel(const void* __restrict__ ei_raw, int n_edges) {
    int e = blockIdx.x * blockDim.x + threadIdx.x;
    if (e >= n_edges) return;
    int src, tgt;
    if (g_is64) {
        const long long* ei = (const long long*)ei_raw;
        src = (int)ei[e];
        tgt = (int)ei[(size_t)n_edges + e];
    } else {
        const int* ei = (const int*)ei_raw;
        src = ei[e];
        tgt = ei[(size_t)n_edges + e];
    }
    int pos = atomicAdd(&g_cursor[src], 1);
    g_stgt[pos] = tgt;
}

// ---------------------------------------------------------------------------
// Kernel 5: segmented gather-reduce + mean. 16 lanes per node; lane j owns
// float4 column j. Writes out exactly once (no atomics, no pre-zero needed).
// ---------------------------------------------------------------------------
__global__ void __launch_bounds__(256) accumulate_kernel(float4* __restrict__ out4,
                                                         int n_nodes)
{
    int t = blockIdx.x * 256 + threadIdx.x;
    int n = t >> 4;
    int j = t & 15;
    if (n >= n_nodes) return;

    int start = g_start[n];
    int deg   = g_hist[n];

    const float4* hp = (const float4*)g_h;
    float4 acc = make_float4(0.f, 0.f, 0.f, 0.f);

    int k = 0;
    for (; k + 2 <= deg; k += 2) {
        int t0 = g_stgt[start + k];
        int t1 = g_stgt[start + k + 1];
        float4 v0 = hp[(size_t)t0 * 16 + j];
        float4 v1 = hp[(size_t)t1 * 16 + j];
        acc.x += v0.x + v1.x;
        acc.y += v0.y + v1.y;
        acc.z += v0.z + v1.z;
        acc.w += v0.w + v1.w;
    }
    if (k < deg) {
        int t0 = g_stgt[start + k];
        float4 v0 = hp[(size_t)t0 * 16 + j];
        acc.x += v0.x; acc.y += v0.y; acc.z += v0.z; acc.w += v0.w;
    }

    float inv = 1.0f / fmaxf((float)deg, 1.0f);
    out4[(size_t)n * 16 + j] = make_float4(acc.x * inv, acc.y * inv,
                                           acc.z * inv, acc.w * inv);
}

// ---------------------------------------------------------------------------
// Launch
// ---------------------------------------------------------------------------
extern "C" void kernel_launch(void* const* d_in, const int* in_sizes, int n_in,
                              void* d_out, int out_size)
{
    const float* x  = (const float*)d_in[0];
    const void*  ei = d_in[1];
    const float* W  = (const float*)d_in[2];
    const float* b  = (const float*)d_in[3];
    float*       out = (float*)d_out;

    int N  = in_sizes[0] / EMBED;          // 100000
    int E  = in_sizes[1] / 2;              // 1600000
    int NB = (N + SCAN_BLK - 1) / SCAN_BLK;

    init_kernel<<<NB, SCAN_BLK>>>((const unsigned long long*)ei, N);
    gemm_relu_kernel<<<(N + 255) / 256, 256>>>(x, W, b, N);
    hist_kernel<<<(E + 255) / 256, 256>>>(ei, E);
    scan1_kernel<<<NB, SCAN_BLK>>>(N);
    scan2_kernel<<<1, 128>>>(NB);
    scan3_kernel<<<NB, SCAN_BLK>>>(N);
    reorder_kernel<<<(E + 255) / 256, 256>>>(ei, E);

    long long at = (long long)N * 16;
    accumulate_kernel<<<(int)((at + 255) / 256), 256>>>((float4*)out, N);
}

// round 4
// speedup vs baseline: 1.4474x; 1.0581x over previous
#include <cuda_runtime.h>
#include <cuda_fp16.h>

#define EMBED 64
#define MAX_NODES 100000
#define MAX_EDGES 1600000
#define SCAN_BLK 1024

// Scratch
__device__ __half g_h[(size_t)MAX_NODES * EMBED];   // relu(x@W^T+b), fp16
__device__ int    g_hist[MAX_NODES];                // degree per src node
__device__ int    g_start[MAX_NODES];               // exclusive scan of hist
__device__ int    g_cursor[MAX_NODES];              // running fill cursor
__device__ int    g_bsum[128];                      // scan block sums
__device__ int    g_stgt[MAX_EDGES];                // tgt indices sorted by src
__device__ int    g_is64;                           // edge_index dtype flag

#define FMA2(acc, a, b) \
    asm("fma.rn.f32x2 %0, %1, %2, %0;" : "+l"(acc) : "l"(a), "l"(b))

__device__ __forceinline__ unsigned long long pack2(float lo, float hi) {
    unsigned long long r;
    asm("mov.b64 %0, {%1, %2};" : "=l"(r) : "f"(lo), "f"(hi));
    return r;
}
__device__ __forceinline__ float unpack_lo(unsigned long long v) {
    float lo, hi;
    asm("mov.b64 {%0, %1}, %2;" : "=f"(lo), "=f"(hi) : "l"(v));
    return lo;
}
__device__ __forceinline__ float unpack_hi(unsigned long long v) {
    float lo, hi;
    asm("mov.b64 {%0, %1}, %2;" : "=f"(lo), "=f"(hi) : "l"(v));
    return hi;
}

// ---------------------------------------------------------------------------
// Kernel 0: zero histogram; thread 0 sniffs edge_index dtype.
// ---------------------------------------------------------------------------
__global__ void init_kernel(const unsigned long long* __restrict__ ei, int n_nodes) {
    int i = blockIdx.x * blockDim.x + threadIdx.x;
    if (i < n_nodes) g_hist[i] = 0;
    if (i == 0) {
        int ok64 = 1;
        #pragma unroll
        for (int k = 0; k < 8; k++) {
            unsigned long long v = ei[k];
            if ((v >> 32) != 0ull || (v & 0xffffffffull) >= (1u << 28)) ok64 = 0;
        }
        g_is64 = ok64;
    }
}

// ---------------------------------------------------------------------------
// Kernel 1: h = relu(x @ W^T + b), packed fma.rn.f32x2, output stored fp16.
// ---------------------------------------------------------------------------
__global__ void __launch_bounds__(256) gemm_relu_kernel(
    const float* __restrict__ x,
    const float* __restrict__ W,
    const float* __restrict__ b,
    int n_nodes)
{
    __shared__ float ws[EMBED * EMBED];   // row-major W[o][d]
    __shared__ float bs[EMBED];

    int tid = threadIdx.x;
    const float4* W4 = (const float4*)W;
    #pragma unroll
    for (int i = tid; i < EMBED * EMBED / 4; i += 256)
        ((float4*)ws)[i] = W4[i];
    if (tid < EMBED) bs[tid] = b[tid];
    __syncthreads();

    int n = blockIdx.x * 256 + tid;
    if (n >= n_nodes) return;

    unsigned long long x2[EMBED / 2];
    const float4* xp = (const float4*)(x + (size_t)n * EMBED);
    #pragma unroll
    for (int i = 0; i < 16; i++) {
        float4 v = xp[i];
        x2[2 * i]     = pack2(v.x, v.y);
        x2[2 * i + 1] = pack2(v.z, v.w);
    }

    uint2* hp = (uint2*)(g_h + (size_t)n * EMBED);   // row = 16 uint2
    #pragma unroll 1
    for (int o = 0; o < EMBED; o += 4) {
        unsigned long long a0 = 0ull, a1 = 0ull, a2 = 0ull, a3 = 0ull;
        const unsigned long long* w0 = (const unsigned long long*)(ws + (o + 0) * EMBED);
        const unsigned long long* w1 = (const unsigned long long*)(ws + (o + 1) * EMBED);
        const unsigned long long* w2 = (const unsigned long long*)(ws + (o + 2) * EMBED);
        const unsigned long long* w3 = (const unsigned long long*)(ws + (o + 3) * EMBED);
        #pragma unroll
        for (int d2 = 0; d2 < EMBED / 2; d2++) {
            unsigned long long xv = x2[d2];
            FMA2(a0, xv, w0[d2]);
            FMA2(a1, xv, w1[d2]);
            FMA2(a2, xv, w2[d2]);
            FMA2(a3, xv, w3[d2]);
        }
        float r0 = fmaxf(bs[o + 0] + unpack_lo(a0) + unpack_hi(a0), 0.f);
        float r1 = fmaxf(bs[o + 1] + unpack_lo(a1) + unpack_hi(a1), 0.f);
        float r2 = fmaxf(bs[o + 2] + unpack_lo(a2) + unpack_hi(a2), 0.f);
        float r3 = fmaxf(bs[o + 3] + unpack_lo(a3) + unpack_hi(a3), 0.f);
        __half2 h01 = __floats2half2_rn(r0, r1);
        __half2 h23 = __floats2half2_rn(r2, r3);
        uint2 st;
        st.x = *(unsigned int*)&h01;
        st.y = *(unsigned int*)&h23;
        hp[o >> 2] = st;
    }
}

// ---------------------------------------------------------------------------
// Kernel 2: histogram of src indices.
// ---------------------------------------------------------------------------
__global__ void hist_kernel(const void* __restrict__ ei_raw, int n_edges) {
    int e = blockIdx.x * blockDim.x + threadIdx.x;
    if (e >= n_edges) return;
    int src = g_is64 ? (int)((const long long*)ei_raw)[e]
                     : ((const int*)ei_raw)[e];
    atomicAdd(&g_hist[src], 1);
}

// ---------------------------------------------------------------------------
// Kernel 3a: per-block exclusive scan via warp shuffles (1024 threads).
// ---------------------------------------------------------------------------
__global__ void __launch_bounds__(SCAN_BLK) scan1_kernel(int n_nodes) {
    __shared__ int wsum[32];
    int t = threadIdx.x;
    int i = blockIdx.x * SCAN_BLK + t;
    int v = (i < n_nodes) ? g_hist[i] : 0;
    int lane = t & 31, w = t >> 5;

    int s = v;
    #pragma unroll
    for (int off = 1; off < 32; off <<= 1) {
        int u = __shfl_up_sync(0xffffffffu, s, off);
        if (lane >= off) s += u;
    }
    if (lane == 31) wsum[w] = s;
    __syncthreads();
    if (w == 0) {
        int ws = wsum[lane];
        #pragma unroll
        for (int off = 1; off < 32; off <<= 1) {
            int u = __shfl_up_sync(0xffffffffu, ws, off);
            if (lane >= off) ws += u;
        }
        wsum[lane] = ws;
    }
    __syncthreads();
    int base = (w > 0) ? wsum[w - 1] : 0;
    int incl = base + s;
    if (i < n_nodes) g_start[i] = incl - v;            // exclusive
    if (t == SCAN_BLK - 1) g_bsum[blockIdx.x] = incl;  // block total
}

// Kernel 3b: exclusive scan of block sums (<=128 blocks).
__global__ void scan2_kernel(int n_blocks) {
    __shared__ int s[128];
    int t = threadIdx.x;
    int v = (t < n_blocks) ? g_bsum[t] : 0;
    s[t] = v;
    __syncthreads();
    #pragma unroll
    for (int off = 1; off < 128; off <<= 1) {
        int add = (t >= off) ? s[t - off] : 0;
        __syncthreads();
        s[t] += add;
        __syncthreads();
    }
    g_bsum[t] = s[t] - v;
}

// Kernel 3c: add block offsets; init cursors.
__global__ void __launch_bounds__(SCAN_BLK) scan3_kernel(int n_nodes) {
    int i = blockIdx.x * SCAN_BLK + threadIdx.x;
    if (i >= n_nodes) return;
    int v = g_start[i] + g_bsum[blockIdx.x];
    g_start[i]  = v;
    g_cursor[i] = v;
}

// ---------------------------------------------------------------------------
// Kernel 4: reorder tgt indices grouped by src.
// ---------------------------------------------------------------------------
__global__ void reorder_kernel(const void* __restrict__ ei_raw, int n_edges) {
    int e = blockIdx.x * blockDim.x + threadIdx.x;
    if (e >= n_edges) return;
    int src, tgt;
    if (g_is64) {
        const long long* ei = (const long long*)ei_raw;
        src = (int)ei[e];
        tgt = (int)ei[(size_t)n_edges + e];
    } else {
        const int* ei = (const int*)ei_raw;
        src = ei[e];
        tgt = ei[(size_t)n_edges + e];
    }
    int pos = atomicAdd(&g_cursor[src], 1);
    g_stgt[pos] = tgt;
}

// ---------------------------------------------------------------------------
// Kernel 5: segmented gather-reduce + mean. 8 lanes per node; lane j owns
// 16 bytes (8 fp16 values) of the 128B row. Accumulate fp32, write once.
// ---------------------------------------------------------------------------
__global__ void __launch_bounds__(256) accumulate_kernel(float4* __restrict__ out4,
                                                         int n_nodes)
{
    int t = blockIdx.x * 256 + threadIdx.x;
    int n = t >> 3;
    int j = t & 7;
    if (n >= n_nodes) return;

    int start = g_start[n];
    int deg   = g_hist[n];

    const uint4* hp = (const uint4*)g_h;   // row = 8 uint4
    float acc[8] = {0.f, 0.f, 0.f, 0.f, 0.f, 0.f, 0.f, 0.f};

    int k = 0;
    for (; k + 2 <= deg; k += 2) {
        int t0 = g_stgt[start + k];
        int t1 = g_stgt[start + k + 1];
        uint4 v0 = hp[(size_t)t0 * 8 + j];
        uint4 v1 = hp[(size_t)t1 * 8 + j];
        #pragma unroll
        for (int q = 0; q < 4; q++) {
            unsigned int u0 = (&v0.x)[q];
            unsigned int u1 = (&v1.x)[q];
            float2 f0 = __half22float2(*(__half2*)&u0);
            float2 f1 = __half22float2(*(__half2*)&u1);
            acc[2 * q]     += f0.x + f1.x;
            acc[2 * q + 1] += f0.y + f1.y;
        }
    }
    if (k < deg) {
        int t0 = g_stgt[start + k];
        uint4 v0 = hp[(size_t)t0 * 8 + j];
        #pragma unroll
        for (int q = 0; q < 4; q++) {
            unsigned int u0 = (&v0.x)[q];
            float2 f0 = __half22float2(*(__half2*)&u0);
            acc[2 * q]     += f0.x;
            acc[2 * q + 1] += f0.y;
        }
    }

    float inv = 1.0f / fmaxf((float)deg, 1.0f);
    size_t base = (size_t)n * 16 + 2 * j;   // lane j owns floats [8j, 8j+8)
    out4[base]     = make_float4(acc[0] * inv, acc[1] * inv, acc[2] * inv, acc[3] * inv);
    out4[base + 1] = make_float4(acc[4] * inv, acc[5] * inv, acc[6] * inv, acc[7] * inv);
}

// ---------------------------------------------------------------------------
// Launch
// ---------------------------------------------------------------------------
extern "C" void kernel_launch(void* const* d_in, const int* in_sizes, int n_in,
                              void* d_out, int out_size)
{
    const float* x  = (const float*)d_in[0];
    const void*  ei = d_in[1];
    const float* W  = (const float*)d_in[2];
    const float* b  = (const float*)d_in[3];
    float*       out = (float*)d_out;

    int N  = in_sizes[0] / EMBED;          // 100000
    int E  = in_sizes[1] / 2;              // 1600000
    int NB = (N + SCAN_BLK - 1) / SCAN_BLK;

    init_kernel<<<NB, SCAN_BLK>>>((const unsigned long long*)ei, N);
    gemm_relu_kernel<<<(N + 255) / 256, 256>>>(x, W, b, N);
    hist_kernel<<<(E + 255) / 256, 256>>>(ei, E);
    scan1_kernel<<<NB, SCAN_BLK>>>(N);
    scan2_kernel<<<1, 128>>>(NB);
    scan3_kernel<<<NB, SCAN_BLK>>>(N);
    reorder_kernel<<<(E + 255) / 256, 256>>>(ei, E);

    long long at = (long long)N * 8;
    accumulate_kernel<<<(int)((at + 255) / 256), 256>>>((float4*)out, N);
}